// round 1
// baseline (speedup 1.0000x reference)
#include <cuda_runtime.h>

// HierarchicalPooling: the reference's _sinkhorn_log returns (u, v) with v
// updated LAST: v = log_b - lse_s(Klog + u). Therefore
//   sum_s exp(u + v + Klog) = exp(v + lse_s(u + Klog)) = exp(log_b)
// i.e. the pooled marginal is exactly the target marginal b = 1/K + 1e-12,
// independent of the input data. This holds for BOTH stages (stage-1 node
// histograms and stage-2 graph histograms), and after normalization the
// output is the constant 1/K_ATOMS = 1/64 everywhere (empty graphs are also
// explicitly set to 1/K). The reference deviates from exact 1/64 only by its
// own fp32 rounding (~5e-5 relative), well inside the 1e-3 gate.

__global__ void HierarchicalPooling_36266703847508_kernel(float4* __restrict__ out4,
                                                          float* __restrict__ out,
                                                          int n) {
    const float v = 1.0f / 64.0f;  // 0.015625f
    int i = blockIdx.x * blockDim.x + threadIdx.x;
    int n4 = n >> 2;
    if (i < n4) {
        out4[i] = make_float4(v, v, v, v);
    }
    // tail (n not divisible by 4) — handled by first few threads
    int tail = n & 3;
    if (i < tail) {
        out[n4 * 4 + i] = v;
    }
}

extern "C" void kernel_launch(void* const* d_in, const int* in_sizes, int n_in,
                              void* d_out, int out_size) {
    (void)d_in; (void)in_sizes; (void)n_in;
    float* out = (float*)d_out;
    int n = out_size;              // expected 64 * 64 = 4096
    int n4 = (n >> 2);
    int threads = 256;
    int blocks = (max(n4, 1) + threads - 1) / threads;
    HierarchicalPooling_36266703847508_kernel<<<blocks, threads>>>(
        (float4*)out, out, n);
}

// round 3
// speedup vs baseline: 1.4375x; 1.4375x over previous
#include <cuda_runtime.h>

// HierarchicalPooling: the reference's _sinkhorn_log updates v LAST:
//   v = log_b - lse_s(Klog + u)
// so sum_s exp(u + v + Klog) = exp(v + lse_s(u + Klog)) = exp(log_b) = b.
// The pooled marginal equals the target marginal b = 1/K + 1e-12 exactly,
// independent of the data, in BOTH Sinkhorn stages. After normalization the
// output is the constant 1/K_ATOMS = 1/64 everywhere (empty graphs too).
// Verified R1: rel_err = 4.2e-7 at 6.6 us. We are at the launch-overhead
// floor; this round strips the kernel to its minimal SASS: address calc +
// one STG.E.128 + EXIT, no guards, no scalar params.

__global__ void __launch_bounds__(128, 1)
HP_fill_exact(float4* __restrict__ out4) {
    const float v = 0.015625f;  // 1/64
    // 8 blocks x 128 threads, one 16B store each -> 4096 floats exactly.
    out4[blockIdx.x * 128 + threadIdx.x] = make_float4(v, v, v, v);
}

// Generic guarded fallback (never used for this problem's fixed shape).
__global__ void HP_fill_generic(float* __restrict__ out, int n) {
    const float v = 0.015625f;
    int i = blockIdx.x * blockDim.x + threadIdx.x;
    if (i < n) out[i] = v;
}

extern "C" void kernel_launch(void* const* d_in, const int* in_sizes, int n_in,
                              void* d_out, int out_size) {
    (void)d_in; (void)in_sizes; (void)n_in;
    if ((out_size & 511) == 0 && out_size > 0) {
        // out_size elements / 4 per store / 128 threads per block
        int blocks = out_size >> 9;   // 4096 -> 8
        HP_fill_exact<<<blocks, 128>>>((float4*)d_out);
    } else {
        int threads = 256;
        int blocks = (out_size + threads - 1) / threads;
        HP_fill_generic<<<blocks, threads>>>((float*)d_out, out_size);
    }
}